// round 12
// baseline (speedup 1.0000x reference)
#include <cuda_runtime.h>
#include <cuda_fp16.h>

// Problem constants
#define NN    16384
#define BB    512
#define NNZE  131072
#define CAP   64                     // padded CSC capacity per column
#define NB    (NN * (size_t)BB)

// Scratch (device globals — no runtime allocation allowed)
__device__ __half g_ha[NB];          // h ping buffer, fp16, (N, B) layout
__device__ __half g_hb[NB];          // h pong buffer, fp16, (N, B) layout
__device__ __half g_c16[NB];         // cell state, fp16, (N, B) layout
__device__ int    g_cnt[NN];         // per-column counts (raw)
__device__ float2 g_ent[NN * CAP];   // entries: {row_as_bits, val_as_half2_bits}
__device__ int    g_is64;            // 1 if sparse_indices is int64, 0 if int32

// ---------------------------------------------------------------------------
// Fast gate math: MUFU.TANH (1 op), sigmoid via tanh identity.
// ---------------------------------------------------------------------------
__device__ __forceinline__ float tanh_ap(float x) {
    float y;
    asm("tanh.approx.f32 %0, %1;" : "=f"(y) : "f"(x));
    return y;
}
__device__ __forceinline__ float sig_ap(float x) {
    return fmaf(0.5f, tanh_ap(0.5f * x), 0.5f);
}

// ---------------------------------------------------------------------------
// Preprocessing: zero counts; detect index dtype (int64 high words all zero).
// ---------------------------------------------------------------------------
__global__ void k_pre(const int* __restrict__ p) {
    unsigned idx = blockIdx.x * 1024 + threadIdx.x;
    g_cnt[idx] = 0;
    if (blockIdx.x == 0 && threadIdx.x < 32) {
        int t = threadIdx.x;
        int nz = 0;
#pragma unroll
        for (int i = 0; i < 16; i++) nz |= p[2 * (t + 32 * i) + 1];
        unsigned m = __ballot_sync(0xffffffffu, nz != 0);
        if (t == 0) g_is64 = (m == 0) ? 1 : 0;
    }
}

__device__ __forceinline__ void get_rc(const void* si, int e, int& r, int& c) {
    if (g_is64) {
        const long long* q = (const long long*)si;
        r = (int)q[2 * e];
        c = (int)q[2 * e + 1];
    } else {
        const int* q = (const int*)si;
        r = q[2 * e];
        c = q[2 * e + 1];
    }
}

// ---------------------------------------------------------------------------
// Padded CSC build: value stored as duplicated half2 bits.
// ---------------------------------------------------------------------------
__global__ void k_build(const void* __restrict__ si, const float* __restrict__ kv) {
    int e = blockIdx.x * 256 + threadIdx.x;
    int r, c;
    get_rc(si, e, r, c);
    int p = atomicAdd(&g_cnt[c], 1);
    if (p < CAP) {
        __half2 h2 = __half2half2(__float2half_rn(kv[e]));
        g_ent[(c << 6) + p] =
            make_float2(__int_as_float(r), __uint_as_float(*reinterpret_cast<unsigned*>(&h2)));
    }
}

// Pad to multiple of 2: zero the single slot at index cnt when cnt is odd.
__global__ void k_fix() {
    int c = blockIdx.x * 1024 + threadIdx.x;
    int cnt = min(g_cnt[c], CAP);
    if (cnt & 1) g_ent[(c << 6) + cnt] = make_float2(0.f, 0.f);
}

// ---------------------------------------------------------------------------
// Transpose in: x (B,N) fp32 -> g_ha (N,B) fp16.
// Tile 64b x 64n, block (32,8), grid (N/64, B/64).
// ---------------------------------------------------------------------------
__global__ void k_init(const float* __restrict__ x) {
    __shared__ float tile[64][65];           // [b_local][n_local]
    int nb = blockIdx.x, bb = blockIdx.y;
    int tx = threadIdx.x, ty = threadIdx.y;
#pragma unroll
    for (int i = 0; i < 8; i++) {
        int b  = bb * 64 + ty + i * 8;
        int n  = nb * 64 + 2 * tx;
        float2 v = *reinterpret_cast<const float2*>(x + (size_t)b * NN + n);
        tile[ty + i * 8][2 * tx]     = v.x;
        tile[ty + i * 8][2 * tx + 1] = v.y;
    }
    __syncthreads();
#pragma unroll
    for (int i = 0; i < 8; i++) {
        int nl = ty * 8 + i;
        int n  = nb * 64 + nl;
        int bl = 2 * tx;
        __half2 hv = __float22half2_rn(make_float2(tile[bl][nl], tile[bl + 1][nl]));
        *reinterpret_cast<__half2*>(g_ha + (size_t)n * BB + bb * 64 + bl) = hv;
    }
}

// Transpose out: g_ha (N,B) fp16 -> out (B,N) fp32. Mirror of k_init.
__global__ void k_out(float* __restrict__ out) {
    __shared__ float tile[64][65];
    int nb = blockIdx.x, bb = blockIdx.y;
    int tx = threadIdx.x, ty = threadIdx.y;
#pragma unroll
    for (int i = 0; i < 8; i++) {
        int nl = ty * 8 + i;
        int n  = nb * 64 + nl;
        int bl = 2 * tx;
        __half2 hv = *reinterpret_cast<const __half2*>(g_ha + (size_t)n * BB + bb * 64 + bl);
        float2 f = __half22float2(hv);
        tile[bl][nl]     = f.x;
        tile[bl + 1][nl] = f.y;
    }
    __syncthreads();
#pragma unroll
    for (int i = 0; i < 8; i++) {
        int b = bb * 64 + ty + i * 8;
        int n = nb * 64 + 2 * tx;
        *reinterpret_cast<float2*>(out + (size_t)b * NN + n) =
            make_float2(tile[ty + i * 8][2 * tx], tile[ty + i * 8][2 * tx + 1]);
    }
}

// ---------------------------------------------------------------------------
// One reservoir iteration. Block = 128 threads = 4 columns x 1 warp.
// Each thread: 16 batch elems (lane*16). Per 2-entry group: 1 entry LDG.128
// + 4 gather LDG.128 (all independent), 16 HFMA2. cnt padded to mult-2
// (k_fix), so no remainder path.
// ---------------------------------------------------------------------------
template<int SRC, bool FIRST, bool LAST>
__global__ void __launch_bounds__(128) k_iter(
    const float* __restrict__ bi, const float* __restrict__ bf,
    const float* __restrict__ bo, const float* __restrict__ bg)
{
    int t    = threadIdx.x;
    int c    = (blockIdx.x << 2) + (t >> 5);
    int lane = t & 31;
    const __half* __restrict__ hin = SRC ? g_hb : g_ha;
    __half* __restrict__ hout      = SRC ? g_ha : g_hb;

    int cnt = (min(__ldg(&g_cnt[c]), CAP) + 1) & ~1;
    const float4* __restrict__ ep = reinterpret_cast<const float4*>(g_ent + (c << 6));

    int boff = lane << 4;                        // 16 batch elements per thread
    __half2 acc[8];
#pragma unroll
    for (int k = 0; k < 8; k++) acc[k] = __half2half2(__ushort_as_half(0));

    for (int e = 0; e < cnt; e += 2) {
        float4 q = __ldg(&ep[e >> 1]);           // 2 entries
        int r0 = __float_as_int(q.x);
        int r1 = __float_as_int(q.z);
        unsigned v0u = __float_as_uint(q.y);
        unsigned v1u = __float_as_uint(q.w);
        __half2 v0 = *reinterpret_cast<__half2*>(&v0u);
        __half2 v1 = *reinterpret_cast<__half2*>(&v1u);

        const __half* p0 = hin + ((r0 << 9) + boff);
        const __half* p1 = hin + ((r1 << 9) + boff);
        uint4 a = *reinterpret_cast<const uint4*>(p0);
        uint4 b = *reinterpret_cast<const uint4*>(p0 + 8);
        uint4 cc = *reinterpret_cast<const uint4*>(p1);
        uint4 d = *reinterpret_cast<const uint4*>(p1 + 8);

        acc[0] = __hfma2(v0, *reinterpret_cast<__half2*>(&a.x), acc[0]);
        acc[1] = __hfma2(v0, *reinterpret_cast<__half2*>(&a.y), acc[1]);
        acc[2] = __hfma2(v0, *reinterpret_cast<__half2*>(&a.z), acc[2]);
        acc[3] = __hfma2(v0, *reinterpret_cast<__half2*>(&a.w), acc[3]);
        acc[4] = __hfma2(v0, *reinterpret_cast<__half2*>(&b.x), acc[4]);
        acc[5] = __hfma2(v0, *reinterpret_cast<__half2*>(&b.y), acc[5]);
        acc[6] = __hfma2(v0, *reinterpret_cast<__half2*>(&b.z), acc[6]);
        acc[7] = __hfma2(v0, *reinterpret_cast<__half2*>(&b.w), acc[7]);
        acc[0] = __hfma2(v1, *reinterpret_cast<__half2*>(&cc.x), acc[0]);
        acc[1] = __hfma2(v1, *reinterpret_cast<__half2*>(&cc.y), acc[1]);
        acc[2] = __hfma2(v1, *reinterpret_cast<__half2*>(&cc.z), acc[2]);
        acc[3] = __hfma2(v1, *reinterpret_cast<__half2*>(&cc.w), acc[3]);
        acc[4] = __hfma2(v1, *reinterpret_cast<__half2*>(&d.x), acc[4]);
        acc[5] = __hfma2(v1, *reinterpret_cast<__half2*>(&d.y), acc[5]);
        acc[6] = __hfma2(v1, *reinterpret_cast<__half2*>(&d.z), acc[6]);
        acc[7] = __hfma2(v1, *reinterpret_cast<__half2*>(&d.w), acc[7]);
    }

    float z[16];
#pragma unroll
    for (int k = 0; k < 8; k++) {
        float2 f = __half22float2(acc[k]);
        z[2 * k]     = f.x;
        z[2 * k + 1] = f.y;
    }

    float vbi = __ldg(&bi[c]), vbf = __ldg(&bf[c]);
    float vbo = __ldg(&bo[c]), vbg = __ldg(&bg[c]);

    size_t o = ((size_t)c << 9) + boff;

    float co[16];
#pragma unroll
    for (int k = 0; k < 16; k++) co[k] = 0.f;
    if (!FIRST) {
        uint4 cu0 = *reinterpret_cast<const uint4*>(g_c16 + o);
        uint4 cu1 = *reinterpret_cast<const uint4*>(g_c16 + o + 8);
        unsigned w[8] = {cu0.x, cu0.y, cu0.z, cu0.w, cu1.x, cu1.y, cu1.z, cu1.w};
#pragma unroll
        for (int k = 0; k < 8; k++) {
            float2 f = __half22float2(*reinterpret_cast<__half2*>(&w[k]));
            co[2 * k]     = f.x;
            co[2 * k + 1] = f.y;
        }
    }

    float cn[16], hn[16];
#pragma unroll
    for (int k = 0; k < 16; k++) {
        float ii = sig_ap(z[k] + vbi);
        float oo = sig_ap(z[k] + vbo);
        float gg = tanh_ap(z[k] + vbg);
        float ig = ii * gg;
        if (FIRST) {
            cn[k] = ig;
        } else {
            float ff = sig_ap(z[k] + vbf);
            cn[k] = fmaf(ff, co[k], ig);
        }
        hn[k] = oo * tanh_ap(cn[k]);
    }

    if (!LAST) {
        unsigned w[8];
#pragma unroll
        for (int k = 0; k < 8; k++) {
            __half2 q = __float22half2_rn(make_float2(cn[2 * k], cn[2 * k + 1]));
            w[k] = *reinterpret_cast<unsigned*>(&q);
        }
        *reinterpret_cast<uint4*>(g_c16 + o)     = make_uint4(w[0], w[1], w[2], w[3]);
        *reinterpret_cast<uint4*>(g_c16 + o + 8) = make_uint4(w[4], w[5], w[6], w[7]);
    }

    {
        unsigned w[8];
#pragma unroll
        for (int k = 0; k < 8; k++) {
            __half2 q = __float22half2_rn(make_float2(hn[2 * k], hn[2 * k + 1]));
            w[k] = *reinterpret_cast<unsigned*>(&q);
        }
        *reinterpret_cast<uint4*>(hout + o)     = make_uint4(w[0], w[1], w[2], w[3]);
        *reinterpret_cast<uint4*>(hout + o + 8) = make_uint4(w[4], w[5], w[6], w[7]);
    }
}

// ---------------------------------------------------------------------------
// Launch
// ---------------------------------------------------------------------------
extern "C" void kernel_launch(void* const* d_in, const int* in_sizes, int n_in,
                              void* d_out, int out_size)
{
    const float* x  = (const float*)d_in[0];
    const float* kv = (const float*)d_in[1];
    const float* bi = (const float*)d_in[2];
    const float* bf = (const float*)d_in[3];
    const float* bo = (const float*)d_in[4];
    const float* bg = (const float*)d_in[5];
    const void*  si = d_in[6];

    // Sparse preprocessing: zero counts (+dtype detect), atomic fill, pad fix
    k_pre<<<NN / 1024, 1024>>>((const int*)si);
    k_build<<<NNZE / 256, 256>>>(si, kv);
    k_fix<<<NN / 1024, 1024>>>();

    // Transpose input to (N,B) fp16
    dim3 tb(32, 8);
    dim3 tg(NN / 64, BB / 64);
    k_init<<<tg, tb>>>(x);

    // 4 reservoir iterations: ha -> hb -> ha -> hb -> ha (all fp16)
    k_iter<0, true,  false><<<NN / 4, 128>>>(bi, bf, bo, bg);
    k_iter<1, false, false><<<NN / 4, 128>>>(bi, bf, bo, bg);
    k_iter<0, false, false><<<NN / 4, 128>>>(bi, bf, bo, bg);
    k_iter<1, false, true ><<<NN / 4, 128>>>(bi, bf, bo, bg);

    // Transpose result (g_ha) back to (B,N) fp32
    k_out<<<tg, tb>>>((float*)d_out);
}

// round 16
// speedup vs baseline: 1.1155x; 1.1155x over previous
#include <cuda_runtime.h>
#include <cuda_fp16.h>

// Problem constants
#define NN    16384
#define BB    512
#define NNZE  131072
#define CAP   64                     // padded CSC capacity per column
#define NB    (NN * (size_t)BB)

// Scratch (device globals — no runtime allocation allowed)
__device__ __half g_ha[NB];          // h ping buffer, fp16, (N, B) layout
__device__ __half g_hb[NB];          // h pong buffer, fp16, (N, B) layout
__device__ __half g_c16[NB];         // cell state, fp16, (N, B) layout
__device__ int    g_cnt[NN];         // per-column counts (raw)
__device__ float2 g_ent[NN * CAP];   // entries: {row_as_bits, val_as_half2_bits}
__device__ int    g_is64;            // 1 if sparse_indices is int64, 0 if int32

// ---------------------------------------------------------------------------
// Fast gate math: MUFU.TANH (1 op), sigmoid via tanh identity.
// ---------------------------------------------------------------------------
__device__ __forceinline__ float tanh_ap(float x) {
    float y;
    asm("tanh.approx.f32 %0, %1;" : "=f"(y) : "f"(x));
    return y;
}
__device__ __forceinline__ float sig_ap(float x) {
    return fmaf(0.5f, tanh_ap(0.5f * x), 0.5f);
}

// ---------------------------------------------------------------------------
// Preprocessing: zero counts; detect index dtype (int64 high words all zero).
// ---------------------------------------------------------------------------
__global__ void k_pre(const int* __restrict__ p) {
    unsigned idx = blockIdx.x * 1024 + threadIdx.x;
    g_cnt[idx] = 0;
    if (blockIdx.x == 0 && threadIdx.x < 32) {
        int t = threadIdx.x;
        int nz = 0;
#pragma unroll
        for (int i = 0; i < 16; i++) nz |= p[2 * (t + 32 * i) + 1];
        unsigned m = __ballot_sync(0xffffffffu, nz != 0);
        if (t == 0) g_is64 = (m == 0) ? 1 : 0;
    }
}

__device__ __forceinline__ void get_rc(const void* si, int e, int& r, int& c) {
    if (g_is64) {
        const long long* q = (const long long*)si;
        r = (int)q[2 * e];
        c = (int)q[2 * e + 1];
    } else {
        const int* q = (const int*)si;
        r = q[2 * e];
        c = q[2 * e + 1];
    }
}

// ---------------------------------------------------------------------------
// Padded CSC build: value stored as duplicated half2 bits.
// ---------------------------------------------------------------------------
__global__ void k_build(const void* __restrict__ si, const float* __restrict__ kv) {
    int e = blockIdx.x * 256 + threadIdx.x;
    int r, c;
    get_rc(si, e, r, c);
    int p = atomicAdd(&g_cnt[c], 1);
    if (p < CAP) {
        __half2 h2 = __half2half2(__float2half_rn(kv[e]));
        g_ent[(c << 6) + p] =
            make_float2(__int_as_float(r), __uint_as_float(*reinterpret_cast<unsigned*>(&h2)));
    }
}

// Pad each column to a multiple of 4 with inert {row 0, val 0} entries.
__global__ void k_fix() {
    int c = blockIdx.x * 1024 + threadIdx.x;
    int cnt = min(g_cnt[c], CAP);
    int cnt4 = min((cnt + 3) & ~3, CAP);
    for (int p = cnt; p < cnt4; ++p)
        g_ent[(c << 6) + p] = make_float2(0.f, 0.f);
}

// ---------------------------------------------------------------------------
// Transpose in: x (B,N) fp32 -> g_ha (N,B) fp16.
// Tile 64b x 64n, block (32,8), grid (N/64, B/64).
// Load phase: float4 (LDG.128); half-warp covers one b-row (64 floats).
// Store phase: half2 STG.32, warp = 128B contiguous.
// ---------------------------------------------------------------------------
__global__ void k_init(const float* __restrict__ x) {
    __shared__ float tile[64][65];           // [b_local][n_local]
    int nb = blockIdx.x, bb = blockIdx.y;
    int tx = threadIdx.x, ty = threadIdx.y;
    int sub = tx >> 4;                       // 0..1: which b-row in this warp
    int l16 = tx & 15;                       // 0..15: float4 index within row
#pragma unroll
    for (int i = 0; i < 4; i++) {
        int bl = ty * 2 + sub + i * 16;
        int b  = bb * 64 + bl;
        int n  = nb * 64 + l16 * 4;
        float4 v = *reinterpret_cast<const float4*>(x + (size_t)b * NN + n);
        tile[bl][l16 * 4 + 0] = v.x;
        tile[bl][l16 * 4 + 1] = v.y;
        tile[bl][l16 * 4 + 2] = v.z;
        tile[bl][l16 * 4 + 3] = v.w;
    }
    __syncthreads();
#pragma unroll
    for (int i = 0; i < 8; i++) {
        int nl = ty * 8 + i;
        int n  = nb * 64 + nl;
        int bl = 2 * tx;
        __half2 hv = __float22half2_rn(make_float2(tile[bl][nl], tile[bl + 1][nl]));
        *reinterpret_cast<__half2*>(g_ha + (size_t)n * BB + bb * 64 + bl) = hv;
    }
}

// ---------------------------------------------------------------------------
// Transpose out: g_ha (N,B) fp16 -> out (B,N) fp32.
// Load phase: uint2 (4 halves); half-warp covers one n-row.
// Store phase: float4 (STG.128); half-warp covers one b-row.
// ---------------------------------------------------------------------------
__global__ void k_out(float* __restrict__ out) {
    __shared__ float tile[64][65];           // [b_local][n_local]
    int nb = blockIdx.x, bb = blockIdx.y;
    int tx = threadIdx.x, ty = threadIdx.y;
    int sub = tx >> 4;
    int l16 = tx & 15;
#pragma unroll
    for (int i = 0; i < 4; i++) {
        int nl = ty * 2 + sub + i * 16;
        int n  = nb * 64 + nl;
        uint2 u = *reinterpret_cast<const uint2*>(g_ha + (size_t)n * BB + bb * 64 + l16 * 4);
        float2 f0 = __half22float2(*reinterpret_cast<__half2*>(&u.x));
        float2 f1 = __half22float2(*reinterpret_cast<__half2*>(&u.y));
        tile[l16 * 4 + 0][nl] = f0.x;
        tile[l16 * 4 + 1][nl] = f0.y;
        tile[l16 * 4 + 2][nl] = f1.x;
        tile[l16 * 4 + 3][nl] = f1.y;
    }
    __syncthreads();
#pragma unroll
    for (int i = 0; i < 4; i++) {
        int bl = ty * 2 + sub + i * 16;
        int b  = bb * 64 + bl;
        float4 v = make_float4(tile[bl][l16 * 4 + 0], tile[bl][l16 * 4 + 1],
                               tile[bl][l16 * 4 + 2], tile[bl][l16 * 4 + 3]);
        *reinterpret_cast<float4*>(out + (size_t)b * NN + nb * 64 + l16 * 4) = v;
    }
}

// ---------------------------------------------------------------------------
// One reservoir iteration (R9-proven shape). Block = 128 threads =
// 2 columns x 64 threads. Each thread: 8 batch elems. HFMA2 accumulation,
// 4 entries per unrolled step, entries fetched 2-per-LDG.128. cnt rounded
// up to mult-4 (pad slots zeroed by k_fix => inert).
// ---------------------------------------------------------------------------
template<int SRC, bool FIRST, bool LAST>
__global__ void __launch_bounds__(128) k_iter(
    const float* __restrict__ bi, const float* __restrict__ bf,
    const float* __restrict__ bo, const float* __restrict__ bg)
{
    int t  = threadIdx.x;
    int c  = (blockIdx.x << 1) + (t >> 6);
    int lt = t & 63;
    const __half* __restrict__ hin = SRC ? g_hb : g_ha;
    __half* __restrict__ hout      = SRC ? g_ha : g_hb;

    int cnt = min((__ldg(&g_cnt[c]) + 3) & ~3, CAP);
    const float4* __restrict__ ep = reinterpret_cast<const float4*>(g_ent + (c << 6));

    int boff = lt << 3;                          // 8 batch elements per thread
    __half2 a0 = __half2half2(__ushort_as_half(0));
    __half2 a1 = a0, a2 = a0, a3 = a0;

    for (int e = 0; e < cnt; e += 4) {
        float4 e01 = __ldg(&ep[(e >> 1)]);
        float4 e23 = __ldg(&ep[(e >> 1) + 1]);
#pragma unroll
        for (int k = 0; k < 4; ++k) {
            float rb = (k == 0) ? e01.x : (k == 1) ? e01.z : (k == 2) ? e23.x : e23.z;
            float vb = (k == 0) ? e01.y : (k == 1) ? e01.w : (k == 2) ? e23.y : e23.w;
            int r = __float_as_int(rb);
            unsigned vu = __float_as_uint(vb);
            __half2 v2 = *reinterpret_cast<__half2*>(&vu);
            uint4 u = *reinterpret_cast<const uint4*>(hin + ((r << 9) + boff));
            a0 = __hfma2(v2, *reinterpret_cast<__half2*>(&u.x), a0);
            a1 = __hfma2(v2, *reinterpret_cast<__half2*>(&u.y), a1);
            a2 = __hfma2(v2, *reinterpret_cast<__half2*>(&u.z), a2);
            a3 = __hfma2(v2, *reinterpret_cast<__half2*>(&u.w), a3);
        }
    }

    float z[8];
    {
        float2 f0 = __half22float2(a0), f1 = __half22float2(a1);
        float2 f2 = __half22float2(a2), f3 = __half22float2(a3);
        z[0] = f0.x; z[1] = f0.y; z[2] = f1.x; z[3] = f1.y;
        z[4] = f2.x; z[5] = f2.y; z[6] = f3.x; z[7] = f3.y;
    }

    float vbi = __ldg(&bi[c]), vbf = __ldg(&bf[c]);
    float vbo = __ldg(&bo[c]), vbg = __ldg(&bg[c]);

    size_t o = ((size_t)c << 9) + boff;

    float co[8] = {0.f, 0.f, 0.f, 0.f, 0.f, 0.f, 0.f, 0.f};
    if (!FIRST) {
        uint4 cu = *reinterpret_cast<const uint4*>(g_c16 + o);
        float2 c0 = __half22float2(*reinterpret_cast<__half2*>(&cu.x));
        float2 c1 = __half22float2(*reinterpret_cast<__half2*>(&cu.y));
        float2 c2 = __half22float2(*reinterpret_cast<__half2*>(&cu.z));
        float2 c3 = __half22float2(*reinterpret_cast<__half2*>(&cu.w));
        co[0] = c0.x; co[1] = c0.y; co[2] = c1.x; co[3] = c1.y;
        co[4] = c2.x; co[5] = c2.y; co[6] = c3.x; co[7] = c3.y;
    }

    float cn[8], hn[8];
#pragma unroll
    for (int k = 0; k < 8; k++) {
        float ii = sig_ap(z[k] + vbi);
        float oo = sig_ap(z[k] + vbo);
        float gg = tanh_ap(z[k] + vbg);
        float ig = ii * gg;
        if (FIRST) {
            cn[k] = ig;
        } else {
            float ff = sig_ap(z[k] + vbf);
            cn[k] = fmaf(ff, co[k], ig);
        }
        hn[k] = oo * tanh_ap(cn[k]);
    }

    if (!LAST) {
        uint4 cu;
        __half2 q0 = __float22half2_rn(make_float2(cn[0], cn[1]));
        __half2 q1 = __float22half2_rn(make_float2(cn[2], cn[3]));
        __half2 q2 = __float22half2_rn(make_float2(cn[4], cn[5]));
        __half2 q3 = __float22half2_rn(make_float2(cn[6], cn[7]));
        cu.x = *reinterpret_cast<unsigned*>(&q0);
        cu.y = *reinterpret_cast<unsigned*>(&q1);
        cu.z = *reinterpret_cast<unsigned*>(&q2);
        cu.w = *reinterpret_cast<unsigned*>(&q3);
        *reinterpret_cast<uint4*>(g_c16 + o) = cu;
    }

    {
        uint4 hu;
        __half2 q0 = __float22half2_rn(make_float2(hn[0], hn[1]));
        __half2 q1 = __float22half2_rn(make_float2(hn[2], hn[3]));
        __half2 q2 = __float22half2_rn(make_float2(hn[4], hn[5]));
        __half2 q3 = __float22half2_rn(make_float2(hn[6], hn[7]));
        hu.x = *reinterpret_cast<unsigned*>(&q0);
        hu.y = *reinterpret_cast<unsigned*>(&q1);
        hu.z = *reinterpret_cast<unsigned*>(&q2);
        hu.w = *reinterpret_cast<unsigned*>(&q3);
        *reinterpret_cast<uint4*>(hout + o) = hu;
    }
}

// ---------------------------------------------------------------------------
// Launch
// ---------------------------------------------------------------------------
extern "C" void kernel_launch(void* const* d_in, const int* in_sizes, int n_in,
                              void* d_out, int out_size)
{
    const float* x  = (const float*)d_in[0];
    const float* kv = (const float*)d_in[1];
    const float* bi = (const float*)d_in[2];
    const float* bf = (const float*)d_in[3];
    const float* bo = (const float*)d_in[4];
    const float* bg = (const float*)d_in[5];
    const void*  si = d_in[6];

    // Sparse preprocessing: zero counts (+dtype detect), atomic fill, pad fix
    k_pre<<<NN / 1024, 1024>>>((const int*)si);
    k_build<<<NNZE / 256, 256>>>(si, kv);
    k_fix<<<NN / 1024, 1024>>>();

    // Transpose input to (N,B) fp16
    dim3 tb(32, 8);
    dim3 tg(NN / 64, BB / 64);
    k_init<<<tg, tb>>>(x);

    // 4 reservoir iterations: ha -> hb -> ha -> hb -> ha (all fp16)
    k_iter<0, true,  false><<<NN / 2, 128>>>(bi, bf, bo, bg);
    k_iter<1, false, false><<<NN / 2, 128>>>(bi, bf, bo, bg);
    k_iter<0, false, false><<<NN / 2, 128>>>(bi, bf, bo, bg);
    k_iter<1, false, true ><<<NN / 2, 128>>>(bi, bf, bo, bg);

    // Transpose result (g_ha) back to (B,N) fp32
    k_out<<<tg, tb>>>((float*)d_out);
}

// round 17
// speedup vs baseline: 1.1347x; 1.0172x over previous
#include <cuda_runtime.h>
#include <cuda_fp16.h>

// Problem constants
#define NN    16384
#define BB    512
#define NNZE  131072
#define CAP   64                     // padded CSC capacity per column
#define NB    (NN * (size_t)BB)

// Scratch (device globals — no runtime allocation allowed)
__device__ __half g_ha[NB];          // h ping buffer, fp16, (N, B) layout
__device__ __half g_hb[NB];          // h pong buffer, fp16, (N, B) layout
__device__ __half g_c16[NB];         // cell state, fp16, (N, B) layout
__device__ int    g_cnt[NN];         // per-column counts (raw)
__device__ float2 g_ent[NN * CAP];   // entries: {row_as_bits, val_as_half2_bits}
__device__ int    g_is64;            // 1 if sparse_indices is int64, 0 if int32

// ---------------------------------------------------------------------------
// Fast gate math: MUFU.TANH (1 op), sigmoid via tanh identity.
// ---------------------------------------------------------------------------
__device__ __forceinline__ float tanh_ap(float x) {
    float y;
    asm("tanh.approx.f32 %0, %1;" : "=f"(y) : "f"(x));
    return y;
}
__device__ __forceinline__ float sig_ap(float x) {
    return fmaf(0.5f, tanh_ap(0.5f * x), 0.5f);
}

// ---------------------------------------------------------------------------
// Preprocessing: zero counts; detect index dtype (int64 high words all zero).
// ---------------------------------------------------------------------------
__global__ void k_pre(const int* __restrict__ p) {
    unsigned idx = blockIdx.x * 1024 + threadIdx.x;
    g_cnt[idx] = 0;
    if (blockIdx.x == 0 && threadIdx.x < 32) {
        int t = threadIdx.x;
        int nz = 0;
#pragma unroll
        for (int i = 0; i < 16; i++) nz |= p[2 * (t + 32 * i) + 1];
        unsigned m = __ballot_sync(0xffffffffu, nz != 0);
        if (t == 0) g_is64 = (m == 0) ? 1 : 0;
    }
}

__device__ __forceinline__ void get_rc(const void* si, int e, int& r, int& c) {
    if (g_is64) {
        const long long* q = (const long long*)si;
        r = (int)q[2 * e];
        c = (int)q[2 * e + 1];
    } else {
        const int* q = (const int*)si;
        r = q[2 * e];
        c = q[2 * e + 1];
    }
}

// ---------------------------------------------------------------------------
// Padded CSC build: value stored as duplicated half2 bits.
// ---------------------------------------------------------------------------
__global__ void k_build(const void* __restrict__ si, const float* __restrict__ kv) {
    int e = blockIdx.x * 256 + threadIdx.x;
    int r, c;
    get_rc(si, e, r, c);
    int p = atomicAdd(&g_cnt[c], 1);
    if (p < CAP) {
        __half2 h2 = __half2half2(__float2half_rn(kv[e]));
        g_ent[(c << 6) + p] =
            make_float2(__int_as_float(r), __uint_as_float(*reinterpret_cast<unsigned*>(&h2)));
    }
}

// Pad each column to a multiple of 4 with inert {row 0, val 0} entries.
__global__ void k_fix() {
    int c = blockIdx.x * 1024 + threadIdx.x;
    int cnt = min(g_cnt[c], CAP);
    int cnt4 = min((cnt + 3) & ~3, CAP);
    for (int p = cnt; p < cnt4; ++p)
        g_ent[(c << 6) + p] = make_float2(0.f, 0.f);
}

// ---------------------------------------------------------------------------
// Transpose in: x (B,N) fp32 -> g_ha (N,B) fp16.
// Tile 64b x 64n, block (32,8), grid (N/64, B/64).
// ---------------------------------------------------------------------------
__global__ void k_init(const float* __restrict__ x) {
    __shared__ float tile[64][65];           // [b_local][n_local]
    int nb = blockIdx.x, bb = blockIdx.y;
    int tx = threadIdx.x, ty = threadIdx.y;
    int sub = tx >> 4;                       // 0..1: which b-row in this warp
    int l16 = tx & 15;                       // 0..15: float4 index within row
#pragma unroll
    for (int i = 0; i < 4; i++) {
        int bl = ty * 2 + sub + i * 16;
        int b  = bb * 64 + bl;
        int n  = nb * 64 + l16 * 4;
        float4 v = *reinterpret_cast<const float4*>(x + (size_t)b * NN + n);
        tile[bl][l16 * 4 + 0] = v.x;
        tile[bl][l16 * 4 + 1] = v.y;
        tile[bl][l16 * 4 + 2] = v.z;
        tile[bl][l16 * 4 + 3] = v.w;
    }
    __syncthreads();
#pragma unroll
    for (int i = 0; i < 8; i++) {
        int nl = ty * 8 + i;
        int n  = nb * 64 + nl;
        int bl = 2 * tx;
        __half2 hv = __float22half2_rn(make_float2(tile[bl][nl], tile[bl + 1][nl]));
        *reinterpret_cast<__half2*>(g_ha + (size_t)n * BB + bb * 64 + bl) = hv;
    }
}

// ---------------------------------------------------------------------------
// Transpose out: g_ha (N,B) fp16 -> out (B,N) fp32.
// ---------------------------------------------------------------------------
__global__ void k_out(float* __restrict__ out) {
    __shared__ float tile[64][65];           // [b_local][n_local]
    int nb = blockIdx.x, bb = blockIdx.y;
    int tx = threadIdx.x, ty = threadIdx.y;
    int sub = tx >> 4;
    int l16 = tx & 15;
#pragma unroll
    for (int i = 0; i < 4; i++) {
        int nl = ty * 2 + sub + i * 16;
        int n  = nb * 64 + nl;
        uint2 u = *reinterpret_cast<const uint2*>(g_ha + (size_t)n * BB + bb * 64 + l16 * 4);
        float2 f0 = __half22float2(*reinterpret_cast<__half2*>(&u.x));
        float2 f1 = __half22float2(*reinterpret_cast<__half2*>(&u.y));
        tile[l16 * 4 + 0][nl] = f0.x;
        tile[l16 * 4 + 1][nl] = f0.y;
        tile[l16 * 4 + 2][nl] = f1.x;
        tile[l16 * 4 + 3][nl] = f1.y;
    }
    __syncthreads();
#pragma unroll
    for (int i = 0; i < 4; i++) {
        int bl = ty * 2 + sub + i * 16;
        int b  = bb * 64 + bl;
        float4 v = make_float4(tile[bl][l16 * 4 + 0], tile[bl][l16 * 4 + 1],
                               tile[bl][l16 * 4 + 2], tile[bl][l16 * 4 + 3]);
        *reinterpret_cast<float4*>(out + (size_t)b * NN + nb * 64 + l16 * 4) = v;
    }
}

// ---------------------------------------------------------------------------
// One reservoir iteration (R9-proven shape). Block = 128 threads =
// 2 columns x 64 threads. Each thread: 8 batch elems.
// ---------------------------------------------------------------------------
template<int SRC, bool FIRST, bool LAST>
__global__ void __launch_bounds__(128) k_iter(
    const float* __restrict__ bi, const float* __restrict__ bf,
    const float* __restrict__ bo, const float* __restrict__ bg)
{
    int t  = threadIdx.x;
    int c  = (blockIdx.x << 1) + (t >> 6);
    int lt = t & 63;
    const __half* __restrict__ hin = SRC ? g_hb : g_ha;
    __half* __restrict__ hout      = SRC ? g_ha : g_hb;

    int cnt = min((__ldg(&g_cnt[c]) + 3) & ~3, CAP);
    const float4* __restrict__ ep = reinterpret_cast<const float4*>(g_ent + (c << 6));

    int boff = lt << 3;                          // 8 batch elements per thread
    __half2 a0 = __half2half2(__ushort_as_half(0));
    __half2 a1 = a0, a2 = a0, a3 = a0;

    for (int e = 0; e < cnt; e += 4) {
        float4 e01 = __ldg(&ep[(e >> 1)]);
        float4 e23 = __ldg(&ep[(e >> 1) + 1]);
#pragma unroll
        for (int k = 0; k < 4; ++k) {
            float rb = (k == 0) ? e01.x : (k == 1) ? e01.z : (k == 2) ? e23.x : e23.z;
            float vb = (k == 0) ? e01.y : (k == 1) ? e01.w : (k == 2) ? e23.y : e23.w;
            int r = __float_as_int(rb);
            unsigned vu = __float_as_uint(vb);
            __half2 v2 = *reinterpret_cast<__half2*>(&vu);
            uint4 u = *reinterpret_cast<const uint4*>(hin + ((r << 9) + boff));
            a0 = __hfma2(v2, *reinterpret_cast<__half2*>(&u.x), a0);
            a1 = __hfma2(v2, *reinterpret_cast<__half2*>(&u.y), a1);
            a2 = __hfma2(v2, *reinterpret_cast<__half2*>(&u.z), a2);
            a3 = __hfma2(v2, *reinterpret_cast<__half2*>(&u.w), a3);
        }
    }

    float z[8];
    {
        float2 f0 = __half22float2(a0), f1 = __half22float2(a1);
        float2 f2 = __half22float2(a2), f3 = __half22float2(a3);
        z[0] = f0.x; z[1] = f0.y; z[2] = f1.x; z[3] = f1.y;
        z[4] = f2.x; z[5] = f2.y; z[6] = f3.x; z[7] = f3.y;
    }

    float vbi = __ldg(&bi[c]), vbf = __ldg(&bf[c]);
    float vbo = __ldg(&bo[c]), vbg = __ldg(&bg[c]);

    size_t o = ((size_t)c << 9) + boff;

    float co[8] = {0.f, 0.f, 0.f, 0.f, 0.f, 0.f, 0.f, 0.f};
    if (!FIRST) {
        uint4 cu = *reinterpret_cast<const uint4*>(g_c16 + o);
        float2 c0 = __half22float2(*reinterpret_cast<__half2*>(&cu.x));
        float2 c1 = __half22float2(*reinterpret_cast<__half2*>(&cu.y));
        float2 c2 = __half22float2(*reinterpret_cast<__half2*>(&cu.z));
        float2 c3 = __half22float2(*reinterpret_cast<__half2*>(&cu.w));
        co[0] = c0.x; co[1] = c0.y; co[2] = c1.x; co[3] = c1.y;
        co[4] = c2.x; co[5] = c2.y; co[6] = c3.x; co[7] = c3.y;
    }

    float cn[8], hn[8];
#pragma unroll
    for (int k = 0; k < 8; k++) {
        float ii = sig_ap(z[k] + vbi);
        float oo = sig_ap(z[k] + vbo);
        float gg = tanh_ap(z[k] + vbg);
        float ig = ii * gg;
        if (FIRST) {
            cn[k] = ig;
        } else {
            float ff = sig_ap(z[k] + vbf);
            cn[k] = fmaf(ff, co[k], ig);
        }
        hn[k] = oo * tanh_ap(cn[k]);
    }

    if (!LAST) {
        uint4 cu;
        __half2 q0 = __float22half2_rn(make_float2(cn[0], cn[1]));
        __half2 q1 = __float22half2_rn(make_float2(cn[2], cn[3]));
        __half2 q2 = __float22half2_rn(make_float2(cn[4], cn[5]));
        __half2 q3 = __float22half2_rn(make_float2(cn[6], cn[7]));
        cu.x = *reinterpret_cast<unsigned*>(&q0);
        cu.y = *reinterpret_cast<unsigned*>(&q1);
        cu.z = *reinterpret_cast<unsigned*>(&q2);
        cu.w = *reinterpret_cast<unsigned*>(&q3);
        *reinterpret_cast<uint4*>(g_c16 + o) = cu;
    }

    {
        uint4 hu;
        __half2 q0 = __float22half2_rn(make_float2(hn[0], hn[1]));
        __half2 q1 = __float22half2_rn(make_float2(hn[2], hn[3]));
        __half2 q2 = __float22half2_rn(make_float2(hn[4], hn[5]));
        __half2 q3 = __float22half2_rn(make_float2(hn[6], hn[7]));
        hu.x = *reinterpret_cast<unsigned*>(&q0);
        hu.y = *reinterpret_cast<unsigned*>(&q1);
        hu.z = *reinterpret_cast<unsigned*>(&q2);
        hu.w = *reinterpret_cast<unsigned*>(&q3);
        *reinterpret_cast<uint4*>(hout + o) = hu;
    }
}

// ---------------------------------------------------------------------------
// Launch. Sparse-build chain (g_cnt/g_ent) is independent of the input
// transpose (x -> g_ha): fork it onto a secondary stream so the two overlap,
// join before iteration 0. Stream/events are created once on the first
// (uncaptured) call; the captured sequence is identical on every call.
// ---------------------------------------------------------------------------
extern "C" void kernel_launch(void* const* d_in, const int* in_sizes, int n_in,
                              void* d_out, int out_size)
{
    const float* x  = (const float*)d_in[0];
    const float* kv = (const float*)d_in[1];
    const float* bi = (const float*)d_in[2];
    const float* bf = (const float*)d_in[3];
    const float* bo = (const float*)d_in[4];
    const float* bg = (const float*)d_in[5];
    const void*  si = d_in[6];

    static cudaStream_t s_side = nullptr;
    static cudaEvent_t  ev_fork = nullptr, ev_join = nullptr;
    if (s_side == nullptr) {
        cudaStreamCreateWithFlags(&s_side, cudaStreamNonBlocking);
        cudaEventCreateWithFlags(&ev_fork, cudaEventDisableTiming);
        cudaEventCreateWithFlags(&ev_join, cudaEventDisableTiming);
    }

    // Fork: sparse preprocessing on the side stream, transpose on the main.
    cudaEventRecord(ev_fork, 0);
    cudaStreamWaitEvent(s_side, ev_fork, 0);

    k_pre<<<NN / 1024, 1024, 0, s_side>>>((const int*)si);
    k_build<<<NNZE / 256, 256, 0, s_side>>>(si, kv);
    k_fix<<<NN / 1024, 1024, 0, s_side>>>();

    dim3 tb(32, 8);
    dim3 tg(NN / 64, BB / 64);
    k_init<<<tg, tb>>>(x);

    // Join before the first iteration.
    cudaEventRecord(ev_join, s_side);
    cudaStreamWaitEvent(0, ev_join, 0);

    // 4 reservoir iterations: ha -> hb -> ha -> hb -> ha (all fp16)
    k_iter<0, true,  false><<<NN / 2, 128>>>(bi, bf, bo, bg);
    k_iter<1, false, false><<<NN / 2, 128>>>(bi, bf, bo, bg);
    k_iter<0, false, false><<<NN / 2, 128>>>(bi, bf, bo, bg);
    k_iter<1, false, true ><<<NN / 2, 128>>>(bi, bf, bo, bg);

    // Transpose result (g_ha) back to (B,N) fp32
    k_out<<<tg, tb>>>((float*)d_out);
}